// round 2
// baseline (speedup 1.0000x reference)
#include <cuda_runtime.h>
#include <cstdint>
#include <cstddef>

#define Bb 64
#define Ss 512
#define Zz 1024
#define H2 256
#define ZS (Zz*Ss)
#define GROUP 32
#define NCH 16   // z-chunks per batch for column partials (Z/64)

// ---------------- static scratch (no allocation allowed) ----------------
__device__ float g_P[(size_t)Bb*ZS];      // 134MB: exp(lc0 + bout)
__device__ float g_v2[Bb*H2];
__device__ float g_elp2[Bb*Ss];           // softmax(s_logits) = exp(lp2)
__device__ float g_ew[Bb*Ss];
__device__ float g_u[Bb*Ss];
__device__ float g_lp1[Zz];
__device__ float g_elp1[Zz];
__device__ float g_iR[Bb*Zz];
__device__ float g_eres[Bb*Zz];
__device__ float g_cp[NCH*Bb*Ss];         // column partials

// ---------------- prior: lp1 = log_softmax(prior) ----------------
__global__ void k_prior(const float* __restrict__ prior) {
    __shared__ float red[1024];
    int tid = threadIdx.x;
    float x = prior[tid];
    red[tid] = x; __syncthreads();
    for (int o = 512; o > 0; o >>= 1) { if (tid < o) red[tid] = fmaxf(red[tid], red[tid+o]); __syncthreads(); }
    float m = red[0]; __syncthreads();
    float e = __expf(x - m);
    red[tid] = e; __syncthreads();
    for (int o = 512; o > 0; o >>= 1) { if (tid < o) red[tid] += red[tid+o]; __syncthreads(); }
    float lse = m + __logf(red[0]);
    float lp1 = x - lse;
    g_lp1[tid] = lp1;
    g_elp1[tid] = __expf(lp1);
}

// ---------------- MLP: softmax -> sigmoid MLP -> v2; also elp2 ----------------
__global__ void k_mlp(const float* __restrict__ sl, const float* __restrict__ W1,
                      const float* __restrict__ b1, const float* __restrict__ W2,
                      const float* __restrict__ b2) {
    __shared__ float sv[Ss];
    __shared__ float v1s[Ss];
    __shared__ float red[Ss];
    int b = blockIdx.x, tid = threadIdx.x;
    float x = sl[b*Ss + tid];
    red[tid] = x; __syncthreads();
    for (int o = 256; o > 0; o >>= 1) { if (tid < o) red[tid] = fmaxf(red[tid], red[tid+o]); __syncthreads(); }
    float m = red[0]; __syncthreads();
    float e = __expf(x - m);
    red[tid] = e; __syncthreads();
    for (int o = 256; o > 0; o >>= 1) { if (tid < o) red[tid] += red[tid+o]; __syncthreads(); }
    float inv = 1.0f / red[0];
    float v = e * inv;
    sv[tid] = v;
    g_elp2[b*Ss + tid] = v;   // exp(log_softmax) = softmax
    __syncthreads();
    // v1 = sigmoid(v @ W1 + b1)  (W1: [S, 512], coalesced over tid)
    float acc = b1[tid];
    #pragma unroll 4
    for (int s = 0; s < Ss; s++) acc = fmaf(sv[s], W1[s*512 + tid], acc);
    v1s[tid] = 1.0f / (1.0f + __expf(-acc));
    __syncthreads();
    // v2 = sigmoid(v1 @ W2 + b2)  (W2: [512, 256])
    if (tid < H2) {
        float a2 = b2[tid];
        #pragma unroll 4
        for (int h = 0; h < 512; h++) a2 = fmaf(v1s[h], W2[h*H2 + tid], a2);
        g_v2[b*H2 + tid] = 1.0f / (1.0f + __expf(-a2));
    }
}

// ---------------- GEMM: P = exp(v2 @ Wout + bout), tf32 mma ----------------
__device__ __forceinline__ void mma8(float* c, uint32_t a0, uint32_t a1, uint32_t a2, uint32_t a3,
                                     uint32_t b0, uint32_t b1) {
    asm volatile(
        "mma.sync.aligned.m16n8k8.row.col.f32.tf32.tf32.f32 "
        "{%0,%1,%2,%3},{%4,%5,%6,%7},{%8,%9},{%0,%1,%2,%3};"
        : "+f"(c[0]), "+f"(c[1]), "+f"(c[2]), "+f"(c[3])
        : "r"(a0), "r"(a1), "r"(a2), "r"(a3), "r"(b0), "r"(b1));
}

__global__ void __launch_bounds__(256) k_gemm(const float* __restrict__ Wout,
                                              const float* __restrict__ bout, int b0) {
    int tid = threadIdx.x, wid = tid >> 5, lane = tid & 31;
    int gid = lane >> 2, tig = lane & 3;
    int warp_m = wid & 1, warp_n = wid >> 1;
    int m0 = b0 + warp_m * 16;
    int n0 = blockIdx.x * 512 + warp_n * 128;

    float c[16][4];
    #pragma unroll
    for (int t = 0; t < 16; t++) { c[t][0]=0.f; c[t][1]=0.f; c[t][2]=0.f; c[t][3]=0.f; }

    for (int k0 = 0; k0 < 256; k0 += 8) {
        uint32_t a0 = __float_as_uint(g_v2[(m0+gid  )*H2 + k0 + tig    ]);
        uint32_t a1 = __float_as_uint(g_v2[(m0+gid+8)*H2 + k0 + tig    ]);
        uint32_t a2 = __float_as_uint(g_v2[(m0+gid  )*H2 + k0 + tig + 4]);
        uint32_t a3 = __float_as_uint(g_v2[(m0+gid+8)*H2 + k0 + tig + 4]);
        const float* Br0 = Wout + (size_t)(k0+tig  )*ZS + n0 + gid;
        const float* Br1 = Wout + (size_t)(k0+tig+4)*ZS + n0 + gid;
        uint32_t bb0[16], bb1[16];
        #pragma unroll
        for (int t = 0; t < 16; t++) {
            bb0[t] = __float_as_uint(__ldg(Br0 + 8*t));
            bb1[t] = __float_as_uint(__ldg(Br1 + 8*t));
        }
        #pragma unroll
        for (int t = 0; t < 16; t++) mma8(c[t], a0, a1, a2, a3, bb0[t], bb1[t]);
    }
    // epilogue: add bout, exponentiate, store P
    #pragma unroll
    for (int t = 0; t < 16; t++) {
        int col = n0 + 8*t + 2*tig;
        float bo0 = bout[col], bo1 = bout[col+1];
        int r0 = m0 + gid, r1 = m0 + gid + 8;
        float2 o0 = { __expf(c[t][0] + bo0), __expf(c[t][1] + bo1) };
        float2 o1 = { __expf(c[t][2] + bo0), __expf(c[t][3] + bo1) };
        *(float2*)&g_P[(size_t)r0*ZS + col] = o0;
        *(float2*)&g_P[(size_t)r1*ZS + col] = o1;
    }
}

// ---------------- fused Sinkhorn iteration (row+col pass) ----------------
// it>0: ew = elp2 / sum(prev col partials)  (col update of iteration it)
// then row sums -> ea = elp1/rowsum, deposit new col partials sum_z P*ea.
// Instance it==10 doubles as the rejection R/Q pass (writes g_iR, g_ew, Q partials).
__global__ void __launch_bounds__(512) k_sink(int it, int b0) {
    int b = b0 + blockIdx.y;
    int chunk = blockIdx.x;         // 0..NCH-1, 64 z-rows each
    int tid = threadIdx.x;
    __shared__ float s_ew[Ss];
    __shared__ float s_col[Ss];
    float ew;
    if (it == 0) {
        ew = 1.0f;
    } else {
        float sum = 0.f;
        #pragma unroll
        for (int cc = 0; cc < NCH; cc++) sum += g_cp[(cc*Bb + b)*Ss + tid];
        ew = g_elp2[b*Ss + tid] / sum;
    }
    s_ew[tid] = ew;
    s_col[tid] = 0.f;
    if (chunk == 0) g_ew[b*Ss + tid] = ew;
    __syncthreads();

    int wid = tid >> 5, lane = tid & 31;
    float ewr[16];
    #pragma unroll
    for (int j = 0; j < 4; j++) {
        float4 e4 = *(const float4*)&s_ew[4*(lane + 32*j)];
        ewr[4*j] = e4.x; ewr[4*j+1] = e4.y; ewr[4*j+2] = e4.z; ewr[4*j+3] = e4.w;
    }
    float colacc[16];
    #pragma unroll
    for (int i = 0; i < 16; i++) colacc[i] = 0.f;

    const float4* Pb = (const float4*)(g_P + (size_t)b*ZS);
    #pragma unroll
    for (int r = 0; r < 4; r++) {
        int z = chunk*64 + wid*4 + r;
        const float4* row = Pb + (size_t)z*128;
        float p[16];
        #pragma unroll
        for (int j = 0; j < 4; j++) {
            float4 v = row[lane + 32*j];
            p[4*j] = v.x; p[4*j+1] = v.y; p[4*j+2] = v.z; p[4*j+3] = v.w;
        }
        float rs = 0.f;
        #pragma unroll
        for (int i = 0; i < 16; i++) rs = fmaf(p[i], ewr[i], rs);
        #pragma unroll
        for (int o = 16; o > 0; o >>= 1) rs += __shfl_xor_sync(0xFFFFFFFFu, rs, o);
        float irs = 1.0f / rs;
        float ea = g_elp1[z] * irs;
        if (lane == 0) g_iR[b*Zz + z] = irs;
        #pragma unroll
        for (int i = 0; i < 16; i++) colacc[i] = fmaf(p[i], ea, colacc[i]);
    }
    #pragma unroll
    for (int j = 0; j < 4; j++)
        #pragma unroll
        for (int i = 0; i < 4; i++)
            atomicAdd(&s_col[4*(lane + 32*j) + i], colacc[4*j + i]);
    __syncthreads();
    g_cp[(chunk*Bb + b)*Ss + tid] = s_col[tid];
}

// ---------------- accept: u_s = ew_s * exp(accept_s - max) ----------------
__global__ void __launch_bounds__(512) k_accept(int b0) {
    int b = b0 + blockIdx.x, tid = threadIdx.x;
    __shared__ float red[Ss];
    float q = 0.f;
    #pragma unroll
    for (int cc = 0; cc < NCH; cc++) q += g_cp[(cc*Bb + b)*Ss + tid];
    float ew = g_ew[b*Ss + tid];
    float A = g_elp2[b*Ss + tid] / (ew * q);
    red[tid] = A; __syncthreads();
    for (int o = 256; o > 0; o >>= 1) { if (tid < o) red[tid] = fmaxf(red[tid], red[tid+o]); __syncthreads(); }
    float mx = red[0];
    g_u[b*Ss + tid] = ew * A / mx;
}

// ---------------- keep: K_z = iR_z * sum_s P*u;  eres = max(0, 1-K) ----------------
__global__ void __launch_bounds__(512) k_keep(int b0) {
    int b = b0 + blockIdx.y, chunk = blockIdx.x, tid = threadIdx.x;
    __shared__ float s_u[Ss];
    s_u[tid] = g_u[b*Ss + tid];
    __syncthreads();
    int wid = tid >> 5, lane = tid & 31;
    float ur[16];
    #pragma unroll
    for (int j = 0; j < 4; j++) {
        float4 e4 = *(const float4*)&s_u[4*(lane + 32*j)];
        ur[4*j] = e4.x; ur[4*j+1] = e4.y; ur[4*j+2] = e4.z; ur[4*j+3] = e4.w;
    }
    const float4* Pb = (const float4*)(g_P + (size_t)b*ZS);
    #pragma unroll
    for (int r = 0; r < 4; r++) {
        int z = chunk*64 + wid*4 + r;
        const float4* row = Pb + (size_t)z*128;
        float ks = 0.f;
        #pragma unroll
        for (int j = 0; j < 4; j++) {
            float4 v = row[lane + 32*j];
            ks = fmaf(v.x, ur[4*j], ks); ks = fmaf(v.y, ur[4*j+1], ks);
            ks = fmaf(v.z, ur[4*j+2], ks); ks = fmaf(v.w, ur[4*j+3], ks);
        }
        #pragma unroll
        for (int o = 16; o > 0; o >>= 1) ks += __shfl_xor_sync(0xFFFFFFFFu, ks, o);
        if (lane == 0) {
            float K = g_iR[b*Zz + z] * ks;
            g_eres[b*Zz + z] = fmaxf(0.f, 1.f - K);
        }
    }
}

// ---------------- final: out = lp1_z + log(P*u_s*iR_z + eres_z*elp2_s) ----------------
__global__ void __launch_bounds__(512) k_final(float* __restrict__ out, int b0) {
    int b = b0 + blockIdx.y, chunk = blockIdx.x, tid = threadIdx.x;
    __shared__ float s_u[Ss];
    __shared__ float s_e2[Ss];
    s_u[tid]  = g_u[b*Ss + tid];
    s_e2[tid] = g_elp2[b*Ss + tid];
    __syncthreads();
    int wid = tid >> 5, lane = tid & 31;
    float ur[16], er[16];
    #pragma unroll
    for (int j = 0; j < 4; j++) {
        float4 u4 = *(const float4*)&s_u[4*(lane + 32*j)];
        ur[4*j] = u4.x; ur[4*j+1] = u4.y; ur[4*j+2] = u4.z; ur[4*j+3] = u4.w;
        float4 e4 = *(const float4*)&s_e2[4*(lane + 32*j)];
        er[4*j] = e4.x; er[4*j+1] = e4.y; er[4*j+2] = e4.z; er[4*j+3] = e4.w;
    }
    const float4* Pb = (const float4*)(g_P + (size_t)b*ZS);
    float4* Ob = (float4*)(out + (size_t)b*ZS);
    #pragma unroll
    for (int r = 0; r < 4; r++) {
        int z = chunk*64 + wid*4 + r;
        float iR = g_iR[b*Zz + z];
        float es = g_eres[b*Zz + z];
        float l1 = g_lp1[z];
        const float4* row = Pb + (size_t)z*128;
        float4* orow = Ob + (size_t)z*128;
        #pragma unroll
        for (int j = 0; j < 4; j++) {
            float4 p = row[lane + 32*j];
            float4 o;
            o.x = l1 + __logf(fmaf(p.x, ur[4*j  ]*iR, es*er[4*j  ]));
            o.y = l1 + __logf(fmaf(p.y, ur[4*j+1]*iR, es*er[4*j+1]));
            o.z = l1 + __logf(fmaf(p.z, ur[4*j+2]*iR, es*er[4*j+2]));
            o.w = l1 + __logf(fmaf(p.w, ur[4*j+3]*iR, es*er[4*j+3]));
            orow[lane + 32*j] = o;
        }
    }
}

// ---------------- launch ----------------
extern "C" void kernel_launch(void* const* d_in, const int* in_sizes, int n_in,
                              void* d_out, int out_size) {
    const float* s_logits = (const float*)d_in[0];
    const float* W1   = (const float*)d_in[1];
    const float* b1   = (const float*)d_in[2];
    const float* W2   = (const float*)d_in[3];
    const float* b2   = (const float*)d_in[4];
    const float* Wout = (const float*)d_in[5];
    const float* bout = (const float*)d_in[6];
    const float* prior= (const float*)d_in[7];
    float* out = (float*)d_out;
    (void)in_sizes; (void)n_in; (void)out_size;

    k_prior<<<1, 1024>>>(prior);
    k_mlp<<<Bb, 512>>>(s_logits, W1, b1, W2, b2);
    for (int g = 0; g < 2; g++) {
        int b0 = g * GROUP;
        k_gemm<<<1024, 256>>>(Wout, bout, b0);
        for (int it = 0; it <= 10; it++)
            k_sink<<<dim3(NCH, GROUP), 512>>>(it, b0);
        k_accept<<<GROUP, 512>>>(b0);
        k_keep<<<dim3(NCH, GROUP), 512>>>(b0);
        k_final<<<dim3(NCH, GROUP), 512>>>(out, b0);
    }
}

// round 3
// speedup vs baseline: 1.2978x; 1.2978x over previous
#include <cuda_runtime.h>
#include <cuda_fp16.h>
#include <cstdint>
#include <cstddef>

#define Bb 64
#define Ss 512
#define Zz 1024
#define H2 256
#define ZS (Zz*Ss)
#define NCH 16   // z-chunks per batch for column partials (Z/64)

// ---------------- static scratch (no allocation allowed) ----------------
__device__ __half g_P[(size_t)Bb*ZS];     // 67MB: exp(lc0 + bout) in fp16
__device__ float g_v2[Bb*H2];
__device__ float g_elp2[Bb*Ss];           // softmax(s_logits) = exp(lp2)
__device__ float g_ew[Bb*Ss];
__device__ float g_u[Bb*Ss];
__device__ float g_lp1[Zz];
__device__ float g_elp1[Zz];
__device__ float g_iR[Bb*Zz];
__device__ float g_cp[NCH*Bb*Ss];         // column partials

// ---------------- prior: lp1 = log_softmax(prior) ----------------
__global__ void k_prior(const float* __restrict__ prior) {
    __shared__ float red[1024];
    int tid = threadIdx.x;
    float x = prior[tid];
    red[tid] = x; __syncthreads();
    for (int o = 512; o > 0; o >>= 1) { if (tid < o) red[tid] = fmaxf(red[tid], red[tid+o]); __syncthreads(); }
    float m = red[0]; __syncthreads();
    float e = __expf(x - m);
    red[tid] = e; __syncthreads();
    for (int o = 512; o > 0; o >>= 1) { if (tid < o) red[tid] += red[tid+o]; __syncthreads(); }
    float lse = m + __logf(red[0]);
    float lp1 = x - lse;
    g_lp1[tid] = lp1;
    g_elp1[tid] = __expf(lp1);
}

// ---------------- MLP: softmax -> sigmoid MLP -> v2; also elp2 ----------------
__global__ void k_mlp(const float* __restrict__ sl, const float* __restrict__ W1,
                      const float* __restrict__ b1, const float* __restrict__ W2,
                      const float* __restrict__ b2) {
    __shared__ float sv[Ss];
    __shared__ float v1s[Ss];
    __shared__ float red[Ss];
    int b = blockIdx.x, tid = threadIdx.x;
    float x = sl[b*Ss + tid];
    red[tid] = x; __syncthreads();
    for (int o = 256; o > 0; o >>= 1) { if (tid < o) red[tid] = fmaxf(red[tid], red[tid+o]); __syncthreads(); }
    float m = red[0]; __syncthreads();
    float e = __expf(x - m);
    red[tid] = e; __syncthreads();
    for (int o = 256; o > 0; o >>= 1) { if (tid < o) red[tid] += red[tid+o]; __syncthreads(); }
    float inv = 1.0f / red[0];
    float v = e * inv;
    sv[tid] = v;
    g_elp2[b*Ss + tid] = v;
    __syncthreads();
    float acc = b1[tid];
    #pragma unroll 4
    for (int s = 0; s < Ss; s++) acc = fmaf(sv[s], W1[s*512 + tid], acc);
    v1s[tid] = 1.0f / (1.0f + __expf(-acc));
    __syncthreads();
    if (tid < H2) {
        float a2 = b2[tid];
        #pragma unroll 4
        for (int h = 0; h < 512; h++) a2 = fmaf(v1s[h], W2[h*H2 + tid], a2);
        g_v2[b*H2 + tid] = 1.0f / (1.0f + __expf(-a2));
    }
}

// ---------------- GEMM: P = exp(v2 @ Wout + bout) -> fp16, tf32 mma, all 64 rows ----------------
__device__ __forceinline__ void mma8(float* c, uint32_t a0, uint32_t a1, uint32_t a2, uint32_t a3,
                                     uint32_t b0, uint32_t b1) {
    asm volatile(
        "mma.sync.aligned.m16n8k8.row.col.f32.tf32.tf32.f32 "
        "{%0,%1,%2,%3},{%4,%5,%6,%7},{%8,%9},{%0,%1,%2,%3};"
        : "+f"(c[0]), "+f"(c[1]), "+f"(c[2]), "+f"(c[3])
        : "r"(a0), "r"(a1), "r"(a2), "r"(a3), "r"(b0), "r"(b1));
}

__global__ void __launch_bounds__(256) k_gemm(const float* __restrict__ Wout,
                                              const float* __restrict__ bout) {
    int tid = threadIdx.x, wid = tid >> 5, lane = tid & 31;
    int gid = lane >> 2, tig = lane & 3;
    int m0 = (wid & 3) * 16;                 // 4 m-tiles cover all 64 rows
    int n0 = blockIdx.x * 256 + (wid >> 2) * 128;

    float c[16][4];
    #pragma unroll
    for (int t = 0; t < 16; t++) { c[t][0]=0.f; c[t][1]=0.f; c[t][2]=0.f; c[t][3]=0.f; }

    for (int k0 = 0; k0 < 256; k0 += 8) {
        uint32_t a0 = __float_as_uint(g_v2[(m0+gid  )*H2 + k0 + tig    ]);
        uint32_t a1 = __float_as_uint(g_v2[(m0+gid+8)*H2 + k0 + tig    ]);
        uint32_t a2 = __float_as_uint(g_v2[(m0+gid  )*H2 + k0 + tig + 4]);
        uint32_t a3 = __float_as_uint(g_v2[(m0+gid+8)*H2 + k0 + tig + 4]);
        const float* Br0 = Wout + (size_t)(k0+tig  )*ZS + n0 + gid;
        const float* Br1 = Wout + (size_t)(k0+tig+4)*ZS + n0 + gid;
        uint32_t bb0[16], bb1[16];
        #pragma unroll
        for (int t = 0; t < 16; t++) {
            bb0[t] = __float_as_uint(__ldg(Br0 + 8*t));
            bb1[t] = __float_as_uint(__ldg(Br1 + 8*t));
        }
        #pragma unroll
        for (int t = 0; t < 16; t++) mma8(c[t], a0, a1, a2, a3, bb0[t], bb1[t]);
    }
    #pragma unroll
    for (int t = 0; t < 16; t++) {
        int col = n0 + 8*t + 2*tig;
        float bo0 = bout[col], bo1 = bout[col+1];
        int r0 = m0 + gid, r1 = m0 + gid + 8;
        __half2 h0 = __floats2half2_rn(__expf(c[t][0] + bo0), __expf(c[t][1] + bo1));
        __half2 h1 = __floats2half2_rn(__expf(c[t][2] + bo0), __expf(c[t][3] + bo1));
        *(__half2*)&g_P[(size_t)r0*ZS + col] = h0;
        *(__half2*)&g_P[(size_t)r1*ZS + col] = h1;
    }
}

// ---------------- helpers ----------------
__device__ __forceinline__ void unpack8(uint4 q, float* p) {
    float2 f;
    f = __half22float2(*(__half2*)&q.x); p[0]=f.x; p[1]=f.y;
    f = __half22float2(*(__half2*)&q.y); p[2]=f.x; p[3]=f.y;
    f = __half22float2(*(__half2*)&q.z); p[4]=f.x; p[5]=f.y;
    f = __half22float2(*(__half2*)&q.w); p[6]=f.x; p[7]=f.y;
}

// ---------------- fused Sinkhorn iteration (row+col pass), fp16 P ----------------
// it>0: ew = elp2 / sum(prev col partials); then row sums -> ea = elp1/rowsum,
// deposit new col partials sum_z P*ea. it==10 doubles as rejection R/Q pass.
__global__ void __launch_bounds__(256, 4) k_sink(int it) {
    int b = blockIdx.y, chunk = blockIdx.x, tid = threadIdx.x;
    __shared__ float s_ew[Ss];
    __shared__ float s_col[Ss];
    #pragma unroll
    for (int h = 0; h < 2; h++) {
        int s = tid + 256*h;
        float ew;
        if (it == 0) ew = 1.0f;
        else {
            float sum = 0.f;
            #pragma unroll
            for (int cc = 0; cc < NCH; cc++) sum += g_cp[(cc*Bb + b)*Ss + s];
            ew = g_elp2[b*Ss + s] / sum;
        }
        s_ew[s] = ew; s_col[s] = 0.f;
        if (chunk == 0) g_ew[b*Ss + s] = ew;
    }
    __syncthreads();

    int wid = tid >> 5, lane = tid & 31;
    float ewr[16], colacc[16];
    #pragma unroll
    for (int i = 0; i < 8; i++) {
        ewr[i]   = s_ew[8*lane + i];
        ewr[8+i] = s_ew[256 + 8*lane + i];
        colacc[i] = 0.f; colacc[8+i] = 0.f;
    }
    const uint4* Pb = (const uint4*)(g_P + (size_t)b*ZS);
    #pragma unroll
    for (int r = 0; r < 8; r++) {
        int z = chunk*64 + wid*8 + r;
        const uint4* row = Pb + (size_t)z*64;
        uint4 q0 = row[lane];
        uint4 q1 = row[lane + 32];
        float p[16];
        unpack8(q0, p); unpack8(q1, p+8);
        float rs = 0.f;
        #pragma unroll
        for (int i = 0; i < 16; i++) rs = fmaf(p[i], ewr[i], rs);
        #pragma unroll
        for (int o = 16; o > 0; o >>= 1) rs += __shfl_xor_sync(0xFFFFFFFFu, rs, o);
        float irs = 1.0f / rs;
        if (lane == 0) g_iR[b*Zz + z] = irs;
        float ea = g_elp1[z] * irs;
        #pragma unroll
        for (int i = 0; i < 16; i++) colacc[i] = fmaf(p[i], ea, colacc[i]);
    }
    #pragma unroll
    for (int i = 0; i < 8; i++) {
        atomicAdd(&s_col[8*lane + i], colacc[i]);
        atomicAdd(&s_col[256 + 8*lane + i], colacc[8+i]);
    }
    __syncthreads();
    #pragma unroll
    for (int h = 0; h < 2; h++) {
        int s = tid + 256*h;
        g_cp[(chunk*Bb + b)*Ss + s] = s_col[s];
    }
}

// ---------------- accept: u_s = ew_s * A_s / max(A) ----------------
__global__ void __launch_bounds__(512) k_accept() {
    int b = blockIdx.x, tid = threadIdx.x;
    __shared__ float red[Ss];
    float q = 0.f;
    #pragma unroll
    for (int cc = 0; cc < NCH; cc++) q += g_cp[(cc*Bb + b)*Ss + tid];
    float ew = g_ew[b*Ss + tid];
    float A = g_elp2[b*Ss + tid] / (ew * q);
    red[tid] = A; __syncthreads();
    for (int o = 256; o > 0; o >>= 1) { if (tid < o) red[tid] = fmaxf(red[tid], red[tid+o]); __syncthreads(); }
    float mx = red[0];
    g_u[b*Ss + tid] = ew * A / mx;
}

// ---------------- fused keep+final ----------------
// per row z: K = iR*sum_s(P*u); eres = max(0,1-K);
// out[z,s] = lp1_z + log(P*u_s*iR + eres*elp2_s)
__global__ void __launch_bounds__(256, 4) k_kf(float* __restrict__ out) {
    int b = blockIdx.y, chunk = blockIdx.x, tid = threadIdx.x;
    __shared__ float s_u[Ss];
    __shared__ float s_e2[Ss];
    #pragma unroll
    for (int h = 0; h < 2; h++) {
        int s = tid + 256*h;
        s_u[s]  = g_u[b*Ss + s];
        s_e2[s] = g_elp2[b*Ss + s];
    }
    __syncthreads();
    int wid = tid >> 5, lane = tid & 31;
    float ur[16], er[16];
    #pragma unroll
    for (int i = 0; i < 8; i++) {
        ur[i]   = s_u[8*lane + i];    ur[8+i] = s_u[256 + 8*lane + i];
        er[i]   = s_e2[8*lane + i];   er[8+i] = s_e2[256 + 8*lane + i];
    }
    const uint4* Pb = (const uint4*)(g_P + (size_t)b*ZS);
    float* Ob = out + (size_t)b*ZS;
    #pragma unroll
    for (int r = 0; r < 8; r++) {
        int z = chunk*64 + wid*8 + r;
        const uint4* row = Pb + (size_t)z*64;
        uint4 q0 = row[lane];
        uint4 q1 = row[lane + 32];
        float p[16];
        unpack8(q0, p); unpack8(q1, p+8);
        float ks = 0.f;
        #pragma unroll
        for (int i = 0; i < 16; i++) ks = fmaf(p[i], ur[i], ks);
        #pragma unroll
        for (int o = 16; o > 0; o >>= 1) ks += __shfl_xor_sync(0xFFFFFFFFu, ks, o);
        float iR = g_iR[b*Zz + z];
        float K = iR * ks;
        float eres = fmaxf(0.f, 1.f - K);
        float l1 = g_lp1[z];
        float v[16];
        #pragma unroll
        for (int i = 0; i < 16; i++)
            v[i] = l1 + __logf(fmaf(p[i], ur[i]*iR, eres*er[i]));
        float* o0 = Ob + (size_t)z*512 + 8*lane;
        float* o1 = o0 + 256;
        *(float4*)(o0    ) = make_float4(v[0], v[1], v[2], v[3]);
        *(float4*)(o0 + 4) = make_float4(v[4], v[5], v[6], v[7]);
        *(float4*)(o1    ) = make_float4(v[8], v[9], v[10], v[11]);
        *(float4*)(o1 + 4) = make_float4(v[12], v[13], v[14], v[15]);
    }
}

// ---------------- launch ----------------
extern "C" void kernel_launch(void* const* d_in, const int* in_sizes, int n_in,
                              void* d_out, int out_size) {
    const float* s_logits = (const float*)d_in[0];
    const float* W1   = (const float*)d_in[1];
    const float* b1   = (const float*)d_in[2];
    const float* W2   = (const float*)d_in[3];
    const float* b2   = (const float*)d_in[4];
    const float* Wout = (const float*)d_in[5];
    const float* bout = (const float*)d_in[6];
    const float* prior= (const float*)d_in[7];
    float* out = (float*)d_out;
    (void)in_sizes; (void)n_in; (void)out_size;

    k_prior<<<1, 1024>>>(prior);
    k_mlp<<<Bb, 512>>>(s_logits, W1, b1, W2, b2);
    k_gemm<<<2048, 256>>>(Wout, bout);
    for (int it = 0; it <= 10; it++)
        k_sink<<<dim3(NCH, Bb), 256>>>(it);
    k_accept<<<Bb, 512>>>();
    k_kf<<<dim3(NCH, Bb), 256>>>(out);
}

// round 5
// speedup vs baseline: 1.3381x; 1.0310x over previous
#include <cuda_runtime.h>
#include <cuda_fp16.h>
#include <cstdint>
#include <cstddef>

#define Bb 64
#define Ss 512
#define Zz 1024
#define H2 256
#define ZS (Zz*Ss)

// ---------------- static scratch ----------------
__device__ __half g_P[(size_t)Bb*ZS];     // 67MB: exp(lc0 + bout) fp16
__device__ float g_v2[Bb*H2];
__device__ float g_elp2[Bb*Ss];
__device__ float g_u[Bb*Ss];
__device__ float g_lp1[Zz];
__device__ float g_elp1[Zz];
__device__ float g_iR[Bb*Zz];

// ---------------- prior: lp1 = log_softmax(prior) ----------------
__global__ void k_prior(const float* __restrict__ prior) {
    __shared__ float red[1024];
    int tid = threadIdx.x;
    float x = prior[tid];
    red[tid] = x; __syncthreads();
    for (int o = 512; o > 0; o >>= 1) { if (tid < o) red[tid] = fmaxf(red[tid], red[tid+o]); __syncthreads(); }
    float m = red[0]; __syncthreads();
    float e = __expf(x - m);
    red[tid] = e; __syncthreads();
    for (int o = 512; o > 0; o >>= 1) { if (tid < o) red[tid] += red[tid+o]; __syncthreads(); }
    float lse = m + __logf(red[0]);
    float lp1 = x - lse;
    g_lp1[tid] = lp1;
    g_elp1[tid] = __expf(lp1);
}

// ---------------- MLP ----------------
__global__ void k_mlp(const float* __restrict__ sl, const float* __restrict__ W1,
                      const float* __restrict__ b1, const float* __restrict__ W2,
                      const float* __restrict__ b2) {
    __shared__ float sv[Ss];
    __shared__ float v1s[Ss];
    __shared__ float red[Ss];
    int b = blockIdx.x, tid = threadIdx.x;
    float x = sl[b*Ss + tid];
    red[tid] = x; __syncthreads();
    for (int o = 256; o > 0; o >>= 1) { if (tid < o) red[tid] = fmaxf(red[tid], red[tid+o]); __syncthreads(); }
    float m = red[0]; __syncthreads();
    float e = __expf(x - m);
    red[tid] = e; __syncthreads();
    for (int o = 256; o > 0; o >>= 1) { if (tid < o) red[tid] += red[tid+o]; __syncthreads(); }
    float inv = 1.0f / red[0];
    float v = e * inv;
    sv[tid] = v;
    g_elp2[b*Ss + tid] = v;
    __syncthreads();
    float acc = b1[tid];
    #pragma unroll 4
    for (int s = 0; s < Ss; s++) acc = fmaf(sv[s], W1[s*512 + tid], acc);
    v1s[tid] = 1.0f / (1.0f + __expf(-acc));
    __syncthreads();
    if (tid < H2) {
        float a2 = b2[tid];
        #pragma unroll 4
        for (int h = 0; h < 512; h++) a2 = fmaf(v1s[h], W2[h*H2 + tid], a2);
        g_v2[b*H2 + tid] = 1.0f / (1.0f + __expf(-a2));
    }
}

// ---------------- GEMM: P = exp(v2 @ Wout + bout) -> fp16, smem-staged tf32 ----------------
__device__ __forceinline__ void mma8(float* c, uint32_t a0, uint32_t a1, uint32_t a2, uint32_t a3,
                                     uint32_t b0, uint32_t b1) {
    asm volatile(
        "mma.sync.aligned.m16n8k8.row.col.f32.tf32.tf32.f32 "
        "{%0,%1,%2,%3},{%4,%5,%6,%7},{%8,%9},{%0,%1,%2,%3};"
        : "+f"(c[0]), "+f"(c[1]), "+f"(c[2]), "+f"(c[3])
        : "r"(a0), "r"(a1), "r"(a2), "r"(a3), "r"(b0), "r"(b1));
}

// block: 256 thr = 8 warps; covers all M=64, N-slice of 256 cols.
// smem union: B double-buffer [2][8][264] fp32 (16.9KB) OR epilogue [64][132] half2 (33.8KB)
__global__ void __launch_bounds__(256, 2) k_gemm(const float* __restrict__ Wout,
                                                 const float* __restrict__ bout) {
    __shared__ __align__(16) unsigned char smem_raw[64 * 132 * 4];
    float (*sB)[8][264] = (float (*)[8][264])smem_raw;
    __half2 (*sO)[132] = (__half2 (*)[132])smem_raw;

    int tid = threadIdx.x, wid = tid >> 5, lane = tid & 31;
    int gid = lane >> 2, tig = lane & 3;
    int n0 = blockIdx.x * 256;

    int kr = tid >> 5;            // 0..7
    int c0 = (tid & 31) * 8;      // 0..248

    float c[4][4][4];
    #pragma unroll
    for (int mt = 0; mt < 4; mt++)
        #pragma unroll
        for (int nt = 0; nt < 4; nt++)
            { c[mt][nt][0]=0.f; c[mt][nt][1]=0.f; c[mt][nt][2]=0.f; c[mt][nt][3]=0.f; }

    const float* src = Wout + (size_t)kr*ZS + n0 + c0;
    float4 t0 = *(const float4*)src;
    float4 t1 = *(const float4*)(src + 4);

    for (int j = 0; j < 32; j++) {
        int buf = j & 1;
        *(float4*)&sB[buf][kr][c0]     = t0;
        *(float4*)&sB[buf][kr][c0 + 4] = t1;
        __syncthreads();
        if (j < 31) {
            const float* s2 = Wout + (size_t)((j+1)*8 + kr)*ZS + n0 + c0;
            t0 = *(const float4*)s2;
            t1 = *(const float4*)(s2 + 4);
        }
        int k0 = j * 8;
        uint32_t a0[4], a1[4], a2[4], a3[4];
        #pragma unroll
        for (int mt = 0; mt < 4; mt++) {
            a0[mt] = __float_as_uint(g_v2[(mt*16+gid  )*H2 + k0 + tig    ]);
            a1[mt] = __float_as_uint(g_v2[(mt*16+gid+8)*H2 + k0 + tig    ]);
            a2[mt] = __float_as_uint(g_v2[(mt*16+gid  )*H2 + k0 + tig + 4]);
            a3[mt] = __float_as_uint(g_v2[(mt*16+gid+8)*H2 + k0 + tig + 4]);
        }
        #pragma unroll
        for (int nt = 0; nt < 4; nt++) {
            int colb = wid*32 + nt*8 + gid;
            uint32_t b0 = __float_as_uint(sB[buf][tig  ][colb]);
            uint32_t b1 = __float_as_uint(sB[buf][tig+4][colb]);
            #pragma unroll
            for (int mt = 0; mt < 4; mt++)
                mma8(c[mt][nt], a0[mt], a1[mt], a2[mt], a3[mt], b0, b1);
        }
        __syncthreads();
    }

    // epilogue: exp(c + bout) -> half2, stage in smem, coalesced copy out
    #pragma unroll
    for (int nt = 0; nt < 4; nt++) {
        int colp = wid*16 + nt*4 + tig;          // half2 index within 128
        float bo0 = bout[n0 + colp*2];
        float bo1 = bout[n0 + colp*2 + 1];
        #pragma unroll
        for (int mt = 0; mt < 4; mt++) {
            int r0 = mt*16 + gid;
            sO[r0  ][colp] = __floats2half2_rn(__expf(c[mt][nt][0]+bo0), __expf(c[mt][nt][1]+bo1));
            sO[r0+8][colp] = __floats2half2_rn(__expf(c[mt][nt][2]+bo0), __expf(c[mt][nt][3]+bo1));
        }
    }
    __syncthreads();
    // copy out: each row = 256 halfs = 512B = 32 uint4; 4 threads/row x 8 passes
    int r = tid >> 2;
    #pragma unroll
    for (int pass = 0; pass < 8; pass++) {
        int u = (tid & 3) + 4*pass;
        uint4 v = *(uint4*)&sO[r][u*4];
        ((uint4*)(g_P + (size_t)r*ZS + n0))[u] = v;
    }
}

// ---------------- helpers ----------------
__device__ __forceinline__ void unpack8(uint4 q, float* p) {
    float2 f;
    f = __half22float2(*(__half2*)&q.x); p[0]=f.x; p[1]=f.y;
    f = __half22float2(*(__half2*)&q.y); p[2]=f.x; p[3]=f.y;
    f = __half22float2(*(__half2*)&q.z); p[4]=f.x; p[5]=f.y;
    f = __half22float2(*(__half2*)&q.w); p[6]=f.x; p[7]=f.y;
}

// ---------------- persistent per-batch Sinkhorn + rejection R/Q + accept ----------------
__global__ void __launch_bounds__(512, 1) k_sinkp() {
    __shared__ float s_ew[Ss];
    __shared__ float s_col[Ss];
    __shared__ float s_elp2[Ss];
    __shared__ float s_elp1[Zz];
    __shared__ float s_part[16][Ss];
    __shared__ float s_red[Ss];

    int b = blockIdx.x, tid = threadIdx.x;
    int w = tid >> 5, lane = tid & 31;

    s_elp2[tid] = g_elp2[b*Ss + tid];
    s_elp1[tid] = g_elp1[tid];
    s_elp1[tid + 512] = g_elp1[tid + 512];
    __syncthreads();

    const uint4* Pb = (const uint4*)(g_P + (size_t)b*ZS);

    for (int it = 0; it <= 10; it++) {
        float ew = (it == 0) ? 1.0f : s_elp2[tid] / s_col[tid];
        s_ew[tid] = ew;
        __syncthreads();

        float ewr[16], colacc[16];
        #pragma unroll
        for (int i = 0; i < 8; i++) {
            ewr[i]   = s_ew[8*lane + i];
            ewr[8+i] = s_ew[256 + 8*lane + i];
            colacc[i] = 0.f; colacc[8+i] = 0.f;
        }
        #pragma unroll 2
        for (int r = 0; r < 64; r++) {
            int z = w*64 + r;
            uint4 q0 = Pb[(size_t)z*64 + lane];
            uint4 q1 = Pb[(size_t)z*64 + 32 + lane];
            float p[16];
            unpack8(q0, p); unpack8(q1, p+8);
            float rs = 0.f;
            #pragma unroll
            for (int i = 0; i < 16; i++) rs = fmaf(p[i], ewr[i], rs);
            #pragma unroll
            for (int o = 16; o > 0; o >>= 1) rs += __shfl_xor_sync(0xFFFFFFFFu, rs, o);
            float irs = 1.0f / rs;
            if (it == 10 && lane == 0) g_iR[b*Zz + z] = irs;
            float ea = s_elp1[z] * irs;
            #pragma unroll
            for (int i = 0; i < 16; i++) colacc[i] = fmaf(p[i], ea, colacc[i]);
        }
        *(float4*)&s_part[w][8*lane]       = make_float4(colacc[0], colacc[1], colacc[2], colacc[3]);
        *(float4*)&s_part[w][8*lane + 4]   = make_float4(colacc[4], colacc[5], colacc[6], colacc[7]);
        *(float4*)&s_part[w][256 + 8*lane]     = make_float4(colacc[8],  colacc[9],  colacc[10], colacc[11]);
        *(float4*)&s_part[w][256 + 8*lane + 4] = make_float4(colacc[12], colacc[13], colacc[14], colacc[15]);
        __syncthreads();
        float sum = 0.f;
        #pragma unroll
        for (int ww = 0; ww < 16; ww++) sum += s_part[ww][tid];
        s_col[tid] = sum;
        __syncthreads();
    }

    // accept: q = s_col (it10 colsum), ew = s_ew (it10)
    float A = s_elp2[tid] / (s_ew[tid] * s_col[tid]);
    s_red[tid] = A; __syncthreads();
    for (int o = 256; o > 0; o >>= 1) { if (tid < o) s_red[tid] = fmaxf(s_red[tid], s_red[tid+o]); __syncthreads(); }
    float mx = s_red[0];
    g_u[b*Ss + tid] = s_ew[tid] * A / mx;
}

// ---------------- fused keep+final ----------------
__global__ void __launch_bounds__(256, 4) k_kf(float* __restrict__ out) {
    int b = blockIdx.y, chunk = blockIdx.x, tid = threadIdx.x;
    __shared__ float s_u[Ss];
    __shared__ float s_e2[Ss];
    #pragma unroll
    for (int h = 0; h < 2; h++) {
        int s = tid + 256*h;
        s_u[s]  = g_u[b*Ss + s];
        s_e2[s] = g_elp2[b*Ss + s];
    }
    __syncthreads();
    int wid = tid >> 5, lane = tid & 31;
    float ur[16], er[16];
    #pragma unroll
    for (int i = 0; i < 8; i++) {
        ur[i]   = s_u[8*lane + i];    ur[8+i] = s_u[256 + 8*lane + i];
        er[i]   = s_e2[8*lane + i];   er[8+i] = s_e2[256 + 8*lane + i];
    }
    const uint4* Pb = (const uint4*)(g_P + (size_t)b*ZS);
    float* Ob = out + (size_t)b*ZS;
    #pragma unroll
    for (int r = 0; r < 8; r++) {
        int z = chunk*64 + wid*8 + r;
        uint4 q0 = Pb[(size_t)z*64 + lane];
        uint4 q1 = Pb[(size_t)z*64 + 32 + lane];
        float p[16];
        unpack8(q0, p); unpack8(q1, p+8);
        float ks = 0.f;
        #pragma unroll
        for (int i = 0; i < 16; i++) ks = fmaf(p[i], ur[i], ks);
        #pragma unroll
        for (int o = 16; o > 0; o >>= 1) ks += __shfl_xor_sync(0xFFFFFFFFu, ks, o);
        float iR = g_iR[b*Zz + z];
        float K = iR * ks;
        float eres = fmaxf(0.f, 1.f - K);
        float l1 = g_lp1[z];
        float v[16];
        #pragma unroll
        for (int i = 0; i < 16; i++)
            v[i] = l1 + __logf(fmaf(p[i], ur[i]*iR, eres*er[i]));
        float* o0 = Ob + (size_t)z*512 + 8*lane;
        float* o1 = o0 + 256;
        *(float4*)(o0    ) = make_float4(v[0], v[1], v[2], v[3]);
        *(float4*)(o0 + 4) = make_float4(v[4], v[5], v[6], v[7]);
        *(float4*)(o1    ) = make_float4(v[8], v[9], v[10], v[11]);
        *(float4*)(o1 + 4) = make_float4(v[12], v[13], v[14], v[15]);
    }
}

// ---------------- launch ----------------
extern "C" void kernel_launch(void* const* d_in, const int* in_sizes, int n_in,
                              void* d_out, int out_size) {
    const float* s_logits = (const float*)d_in[0];
    const float* W1   = (const float*)d_in[1];
    const float* b1   = (const float*)d_in[2];
    const float* W2   = (const float*)d_in[3];
    const float* b2   = (const float*)d_in[4];
    const float* Wout = (const float*)d_in[5];
    const float* bout = (const float*)d_in[6];
    const float* prior= (const float*)d_in[7];
    float* out = (float*)d_out;
    (void)in_sizes; (void)n_in; (void)out_size;

    k_prior<<<1, 1024>>>(prior);
    k_mlp<<<Bb, 512>>>(s_logits, W1, b1, W2, b2);
    k_gemm<<<2048, 256>>>(Wout, bout);
    k_sinkp<<<Bb, 512>>>();
    k_kf<<<dim3(16, Bb), 256>>>(out);
}

// round 6
// speedup vs baseline: 1.7640x; 1.3183x over previous
#include <cuda_runtime.h>
#include <cuda_fp16.h>
#include <cstdint>
#include <cstddef>

#define Bb 64
#define Ss 512
#define Zz 1024
#define H2 256
#define ZS (Zz*Ss)

// ---------------- static scratch ----------------
__device__ __half g_P[(size_t)Bb*ZS];     // 67MB: exp(lc0 + bout) fp16
__device__ float g_v2[Bb*H2];
__device__ float g_elp2[Bb*Ss];
__device__ float g_u[Bb*Ss];
__device__ float g_lp1[Zz];
__device__ float g_elp1[Zz];
__device__ float g_iR[Bb*Zz];
__device__ float g_cph[2][Bb*Ss];         // per-half column partials
__device__ int   g_bar[Bb];               // cross-CTA barrier counters

// ---------------- zero barrier counters (each graph replay) ----------------
__global__ void k_zero() { g_bar[threadIdx.x] = 0; }

// ---------------- prior: lp1 = log_softmax(prior) ----------------
__global__ void k_prior(const float* __restrict__ prior) {
    __shared__ float red[1024];
    int tid = threadIdx.x;
    float x = prior[tid];
    red[tid] = x; __syncthreads();
    for (int o = 512; o > 0; o >>= 1) { if (tid < o) red[tid] = fmaxf(red[tid], red[tid+o]); __syncthreads(); }
    float m = red[0]; __syncthreads();
    float e = __expf(x - m);
    red[tid] = e; __syncthreads();
    for (int o = 512; o > 0; o >>= 1) { if (tid < o) red[tid] += red[tid+o]; __syncthreads(); }
    float lse = m + __logf(red[0]);
    float lp1 = x - lse;
    g_lp1[tid] = lp1;
    g_elp1[tid] = __expf(lp1);
}

// ---------------- MLP ----------------
__global__ void k_mlp(const float* __restrict__ sl, const float* __restrict__ W1,
                      const float* __restrict__ b1, const float* __restrict__ W2,
                      const float* __restrict__ b2) {
    __shared__ float sv[Ss];
    __shared__ float v1s[Ss];
    __shared__ float red[Ss];
    int b = blockIdx.x, tid = threadIdx.x;
    float x = sl[b*Ss + tid];
    red[tid] = x; __syncthreads();
    for (int o = 256; o > 0; o >>= 1) { if (tid < o) red[tid] = fmaxf(red[tid], red[tid+o]); __syncthreads(); }
    float m = red[0]; __syncthreads();
    float e = __expf(x - m);
    red[tid] = e; __syncthreads();
    for (int o = 256; o > 0; o >>= 1) { if (tid < o) red[tid] += red[tid+o]; __syncthreads(); }
    float inv = 1.0f / red[0];
    float v = e * inv;
    sv[tid] = v;
    g_elp2[b*Ss + tid] = v;
    __syncthreads();
    float acc = b1[tid];
    #pragma unroll 4
    for (int s = 0; s < Ss; s++) acc = fmaf(sv[s], W1[s*512 + tid], acc);
    v1s[tid] = 1.0f / (1.0f + __expf(-acc));
    __syncthreads();
    if (tid < H2) {
        float a2 = b2[tid];
        #pragma unroll 4
        for (int h = 0; h < 512; h++) a2 = fmaf(v1s[h], W2[h*H2 + tid], a2);
        g_v2[b*H2 + tid] = 1.0f / (1.0f + __expf(-a2));
    }
}

// ---------------- GEMM: P = exp(v2 @ Wout + bout) -> fp16, cp.async 4-stage ----------------
__device__ __forceinline__ void mma8(float* c, uint32_t a0, uint32_t a1, uint32_t a2, uint32_t a3,
                                     uint32_t b0, uint32_t b1) {
    asm volatile(
        "mma.sync.aligned.m16n8k8.row.col.f32.tf32.tf32.f32 "
        "{%0,%1,%2,%3},{%4,%5,%6,%7},{%8,%9},{%0,%1,%2,%3};"
        : "+f"(c[0]), "+f"(c[1]), "+f"(c[2]), "+f"(c[3])
        : "r"(a0), "r"(a1), "r"(a2), "r"(a3), "r"(b0), "r"(b1));
}

__device__ __forceinline__ void cp16(uint32_t saddr, const void* gptr) {
    asm volatile("cp.async.cg.shared.global [%0], [%1], 16;" :: "r"(saddr), "l"(gptr));
}

// block: 256 thr = 8 warps; all M=64 x N-slice 256.
// smem union: B 4-stage [4][8][264] fp32 (33.8KB) OR epilogue [64][132] half2 (33.8KB)
__global__ void __launch_bounds__(256, 2) k_gemm(const float* __restrict__ Wout,
                                                 const float* __restrict__ bout) {
    __shared__ __align__(16) unsigned char smem_raw[4 * 8 * 264 * 4];
    float (*sB)[8][264] = (float (*)[8][264])smem_raw;
    __half2 (*sO)[132] = (__half2 (*)[132])smem_raw;
    uint32_t sbase = (uint32_t)__cvta_generic_to_shared(smem_raw);

    int tid = threadIdx.x, wid = tid >> 5, lane = tid & 31;
    int gid = lane >> 2, tig = lane & 3;
    int n0 = blockIdx.x * 256;

    int kr = tid >> 5;            // 0..7 k-row within stage
    int c0 = (tid & 31) * 8;      // 0..248 col

    float c[4][4][4];
    #pragma unroll
    for (int mt = 0; mt < 4; mt++)
        #pragma unroll
        for (int nt = 0; nt < 4; nt++)
            { c[mt][nt][0]=0.f; c[mt][nt][1]=0.f; c[mt][nt][2]=0.f; c[mt][nt][3]=0.f; }

    // prologue: issue stages 0..2
    #pragma unroll
    for (int s = 0; s < 3; s++) {
        const float* src = Wout + (size_t)(s*8 + kr)*ZS + n0 + c0;
        uint32_t dst = sbase + (uint32_t)((s*8 + kr)*264 + c0) * 4u;
        cp16(dst, src);
        cp16(dst + 16, src + 4);
        asm volatile("cp.async.commit_group;");
    }

    for (int j = 0; j < 32; j++) {
        asm volatile("cp.async.wait_group 2;");
        __syncthreads();
        if (j + 3 < 32) {
            int s = (j + 3) & 3;
            const float* src = Wout + (size_t)((j+3)*8 + kr)*ZS + n0 + c0;
            uint32_t dst = sbase + (uint32_t)((s*8 + kr)*264 + c0) * 4u;
            cp16(dst, src);
            cp16(dst + 16, src + 4);
            asm volatile("cp.async.commit_group;");
        }
        int buf = j & 3;
        int k0 = j * 8;
        uint32_t a0[4], a1[4], a2[4], a3[4];
        #pragma unroll
        for (int mt = 0; mt < 4; mt++) {
            a0[mt] = __float_as_uint(g_v2[(mt*16+gid  )*H2 + k0 + tig    ]);
            a1[mt] = __float_as_uint(g_v2[(mt*16+gid+8)*H2 + k0 + tig    ]);
            a2[mt] = __float_as_uint(g_v2[(mt*16+gid  )*H2 + k0 + tig + 4]);
            a3[mt] = __float_as_uint(g_v2[(mt*16+gid+8)*H2 + k0 + tig + 4]);
        }
        #pragma unroll
        for (int nt = 0; nt < 4; nt++) {
            int colb = wid*32 + nt*8 + gid;
            uint32_t b0 = __float_as_uint(sB[buf][tig  ][colb]);
            uint32_t b1 = __float_as_uint(sB[buf][tig+4][colb]);
            #pragma unroll
            for (int mt = 0; mt < 4; mt++)
                mma8(c[mt][nt], a0[mt], a1[mt], a2[mt], a3[mt], b0, b1);
        }
    }
    __syncthreads();   // all reads of sB done before epilogue reuses smem

    // epilogue: exp(c + bout) -> half2, stage in smem, coalesced copy out
    #pragma unroll
    for (int nt = 0; nt < 4; nt++) {
        int colp = wid*16 + nt*4 + tig;
        float bo0 = bout[n0 + colp*2];
        float bo1 = bout[n0 + colp*2 + 1];
        #pragma unroll
        for (int mt = 0; mt < 4; mt++) {
            int r0 = mt*16 + gid;
            sO[r0  ][colp] = __floats2half2_rn(__expf(c[mt][nt][0]+bo0), __expf(c[mt][nt][1]+bo1));
            sO[r0+8][colp] = __floats2half2_rn(__expf(c[mt][nt][2]+bo0), __expf(c[mt][nt][3]+bo1));
        }
    }
    __syncthreads();
    int r = tid >> 2;
    #pragma unroll
    for (int pass = 0; pass < 8; pass++) {
        int u = (tid & 3) + 4*pass;
        uint4 v = *(uint4*)&sO[r][u*4];
        ((uint4*)(g_P + (size_t)r*ZS + n0))[u] = v;
    }
}

// ---------------- helpers ----------------
__device__ __forceinline__ void unpack8(uint4 q, float* p) {
    float2 f;
    f = __half22float2(*(__half2*)&q.x); p[0]=f.x; p[1]=f.y;
    f = __half22float2(*(__half2*)&q.y); p[2]=f.x; p[3]=f.y;
    f = __half22float2(*(__half2*)&q.z); p[4]=f.x; p[5]=f.y;
    f = __half22float2(*(__half2*)&q.w); p[6]=f.x; p[7]=f.y;
}

// ---------------- persistent Sinkhorn, 2 CTAs/batch with cross-CTA barrier ----------------
// grid = 128: blockIdx.x = batch*2 + half. Each CTA: 512 z-rows (16 warps x 32).
__global__ void __launch_bounds__(512, 1) k_sinkp2() {
    __shared__ float s_ew[Ss];
    __shared__ float s_col[Ss];
    __shared__ float s_elp2[Ss];
    __shared__ float s_elp1h[Ss];
    __shared__ float s_part[16][Ss];
    __shared__ float s_red[Ss];

    int b = blockIdx.x >> 1, half = blockIdx.x & 1;
    int tid = threadIdx.x;
    int w = tid >> 5, lane = tid & 31;

    s_elp2[tid]  = g_elp2[b*Ss + tid];
    s_elp1h[tid] = g_elp1[half*512 + tid];
    __syncthreads();

    const uint4* Pb = (const uint4*)(g_P + (size_t)b*ZS);
    float my_part = 0.f;

    for (int it = 0; it <= 10; it++) {
        float ew;
        if (it == 0) ew = 1.0f;
        else {
            float other = g_cph[1 - half][b*Ss + tid];
            s_col[tid] = my_part + other;
            ew = s_elp2[tid] / (my_part + other);
        }
        s_ew[tid] = ew;
        __syncthreads();

        float ewr[16], colacc[16];
        #pragma unroll
        for (int i = 0; i < 8; i++) {
            ewr[i]   = s_ew[8*lane + i];
            ewr[8+i] = s_ew[256 + 8*lane + i];
            colacc[i] = 0.f; colacc[8+i] = 0.f;
        }
        #pragma unroll
        for (int rq = 0; rq < 8; rq++) {
            int zl = w*32 + rq*4;                 // local row base (within half)
            uint4 q[8];
            #pragma unroll
            for (int rr = 0; rr < 4; rr++) {
                const uint4* row = Pb + (size_t)(half*512 + zl + rr)*64;
                q[2*rr]   = row[lane];
                q[2*rr+1] = row[lane + 32];
            }
            #pragma unroll
            for (int rr = 0; rr < 4; rr++) {
                float p[16];
                unpack8(q[2*rr], p); unpack8(q[2*rr+1], p+8);
                float rs = 0.f;
                #pragma unroll
                for (int i = 0; i < 16; i++) rs = fmaf(p[i], ewr[i], rs);
                #pragma unroll
                for (int o = 16; o > 0; o >>= 1) rs += __shfl_xor_sync(0xFFFFFFFFu, rs, o);
                float irs = 1.0f / rs;
                int zg = half*512 + zl + rr;
                if (it == 10 && lane == 0) g_iR[b*Zz + zg] = irs;
                float ea = s_elp1h[zl + rr] * irs;
                #pragma unroll
                for (int i = 0; i < 16; i++) colacc[i] = fmaf(p[i], ea, colacc[i]);
            }
        }
        *(float4*)&s_part[w][8*lane]           = make_float4(colacc[0],  colacc[1],  colacc[2],  colacc[3]);
        *(float4*)&s_part[w][8*lane + 4]       = make_float4(colacc[4],  colacc[5],  colacc[6],  colacc[7]);
        *(float4*)&s_part[w][256 + 8*lane]     = make_float4(colacc[8],  colacc[9],  colacc[10], colacc[11]);
        *(float4*)&s_part[w][256 + 8*lane + 4] = make_float4(colacc[12], colacc[13], colacc[14], colacc[15]);
        __syncthreads();
        float sum = 0.f;
        #pragma unroll
        for (int ww = 0; ww < 16; ww++) sum += s_part[ww][tid];
        my_part = sum;
        g_cph[half][b*Ss + tid] = sum;
        __syncthreads();
        // cross-CTA barrier (release: fence+atomic; acquire: atomic spin + fence)
        if (tid == 0) {
            __threadfence();
            atomicAdd(&g_bar[b], 1);
            int target = 2 * (it + 1);
            while (atomicAdd(&g_bar[b], 0) < target) { }
            __threadfence();
        }
        __syncthreads();
    }

    // final col update + accept (both CTAs compute; half 0 writes)
    float other = g_cph[1 - half][b*Ss + tid];
    float colsum = my_part + other;
    float A = s_elp2[tid] / (s_ew[tid] * colsum);
    s_red[tid] = A; __syncthreads();
    for (int o = 256; o > 0; o >>= 1) { if (tid < o) s_red[tid] = fmaxf(s_red[tid], s_red[tid+o]); __syncthreads(); }
    float mx = s_red[0];
    if (half == 0) g_u[b*Ss + tid] = s_ew[tid] * A / mx;
}

// ---------------- fused keep+final ----------------
__global__ void __launch_bounds__(256, 4) k_kf(float* __restrict__ out) {
    int b = blockIdx.y, chunk = blockIdx.x, tid = threadIdx.x;
    __shared__ float s_u[Ss];
    __shared__ float s_e2[Ss];
    #pragma unroll
    for (int h = 0; h < 2; h++) {
        int s = tid + 256*h;
        s_u[s]  = g_u[b*Ss + s];
        s_e2[s] = g_elp2[b*Ss + s];
    }
    __syncthreads();
    int wid = tid >> 5, lane = tid & 31;
    float ur[16], er[16];
    #pragma unroll
    for (int i = 0; i < 8; i++) {
        ur[i]   = s_u[8*lane + i];    ur[8+i] = s_u[256 + 8*lane + i];
        er[i]   = s_e2[8*lane + i];   er[8+i] = s_e2[256 + 8*lane + i];
    }
    const uint4* Pb = (const uint4*)(g_P + (size_t)b*ZS);
    float* Ob = out + (size_t)b*ZS;
    #pragma unroll
    for (int r = 0; r < 8; r++) {
        int z = chunk*64 + wid*8 + r;
        uint4 q0 = Pb[(size_t)z*64 + lane];
        uint4 q1 = Pb[(size_t)z*64 + 32 + lane];
        float p[16];
        unpack8(q0, p); unpack8(q1, p+8);
        float ks = 0.f;
        #pragma unroll
        for (int i = 0; i < 16; i++) ks = fmaf(p[i], ur[i], ks);
        #pragma unroll
        for (int o = 16; o > 0; o >>= 1) ks += __shfl_xor_sync(0xFFFFFFFFu, ks, o);
        float iR = g_iR[b*Zz + z];
        float K = iR * ks;
        float eres = fmaxf(0.f, 1.f - K);
        float l1 = g_lp1[z];
        float v[16];
        #pragma unroll
        for (int i = 0; i < 16; i++)
            v[i] = l1 + __logf(fmaf(p[i], ur[i]*iR, eres*er[i]));
        float* o0 = Ob + (size_t)z*512 + 8*lane;
        float* o1 = o0 + 256;
        *(float4*)(o0    ) = make_float4(v[0], v[1], v[2], v[3]);
        *(float4*)(o0 + 4) = make_float4(v[4], v[5], v[6], v[7]);
        *(float4*)(o1    ) = make_float4(v[8], v[9], v[10], v[11]);
        *(float4*)(o1 + 4) = make_float4(v[12], v[13], v[14], v[15]);
    }
}

// ---------------- launch ----------------
extern "C" void kernel_launch(void* const* d_in, const int* in_sizes, int n_in,
                              void* d_out, int out_size) {
    const float* s_logits = (const float*)d_in[0];
    const float* W1   = (const float*)d_in[1];
    const float* b1   = (const float*)d_in[2];
    const float* W2   = (const float*)d_in[3];
    const float* b2   = (const float*)d_in[4];
    const float* Wout = (const float*)d_in[5];
    const float* bout = (const float*)d_in[6];
    const float* prior= (const float*)d_in[7];
    float* out = (float*)d_out;
    (void)in_sizes; (void)n_in; (void)out_size;

    k_zero<<<1, Bb>>>();
    k_prior<<<1, 1024>>>(prior);
    k_mlp<<<Bb, 512>>>(s_logits, W1, b1, W2, b2);
    k_gemm<<<2048, 256>>>(Wout, bout);
    k_sinkp2<<<2*Bb, 512>>>();
    k_kf<<<dim3(16, Bb), 256>>>(out);
}

// round 12
// speedup vs baseline: 2.4555x; 1.3920x over previous
#include <cuda_runtime.h>
#include <cuda_fp16.h>
#include <cstdint>
#include <cstddef>

#define Bb 64
#define Ss 512
#define Zz 1024
#define H2 256
#define ZS (Zz*Ss)

// ---------------- static scratch ----------------
__device__ __half g_P[(size_t)Bb*ZS];     // 67MB: exp(lc0 + bout) fp16
__device__ float g_v2[Bb*H2];
__device__ float g_elp2[Bb*Ss];
__device__ float g_u[Bb*Ss];
__device__ float g_lp1[Zz];
__device__ float g_elp1[Zz];
__device__ float g_iR[Bb*Zz];
__device__ float g_cph[2][Bb*Ss];         // per-half column partials
__device__ int   g_bar[Bb];               // cross-CTA barrier counters

// smem layout for k_gemm (dynamic):
//   [0, 66560)        sA: float[64][260]  (A staged, padded for conflict-free frag reads)
//   [66560, 100352)   sB: float[4][8][264] (B 4-stage)  UNION  sO: __half2[64][132]
#define SMEM_B_OFF    66560
#define SMEM_TOTAL_GEMM 100352

// ---------------- zero barrier counters (each graph replay) ----------------
__global__ void k_zero() { g_bar[threadIdx.x] = 0; }

// ---------------- prior: lp1 = log_softmax(prior) ----------------
__global__ void k_prior(const float* __restrict__ prior) {
    __shared__ float red[1024];
    int tid = threadIdx.x;
    float x = prior[tid];
    red[tid] = x; __syncthreads();
    for (int o = 512; o > 0; o >>= 1) { if (tid < o) red[tid] = fmaxf(red[tid], red[tid+o]); __syncthreads(); }
    float m = red[0]; __syncthreads();
    float e = __expf(x - m);
    red[tid] = e; __syncthreads();
    for (int o = 512; o > 0; o >>= 1) { if (tid < o) red[tid] += red[tid+o]; __syncthreads(); }
    float lse = m + __logf(red[0]);
    float lp1 = x - lse;
    g_lp1[tid] = lp1;
    g_elp1[tid] = __expf(lp1);
}

// ---------------- MLP ----------------
__global__ void k_mlp(const float* __restrict__ sl, const float* __restrict__ W1,
                      const float* __restrict__ b1, const float* __restrict__ W2,
                      const float* __restrict__ b2) {
    __shared__ float sv[Ss];
    __shared__ float v1s[Ss];
    __shared__ float red[Ss];
    int b = blockIdx.x, tid = threadIdx.x;
    float x = sl[b*Ss + tid];
    red[tid] = x; __syncthreads();
    for (int o = 256; o > 0; o >>= 1) { if (tid < o) red[tid] = fmaxf(red[tid], red[tid+o]); __syncthreads(); }
    float m = red[0]; __syncthreads();
    float e = __expf(x - m);
    red[tid] = e; __syncthreads();
    for (int o = 256; o > 0; o >>= 1) { if (tid < o) red[tid] += red[tid+o]; __syncthreads(); }
    float inv = 1.0f / red[0];
    float v = e * inv;
    sv[tid] = v;
    g_elp2[b*Ss + tid] = v;
    __syncthreads();
    float acc = b1[tid];
    #pragma unroll 4
    for (int s = 0; s < Ss; s++) acc = fmaf(sv[s], W1[s*512 + tid], acc);
    v1s[tid] = 1.0f / (1.0f + __expf(-acc));
    __syncthreads();
    if (tid < H2) {
        float a2 = b2[tid];
        #pragma unroll 4
        for (int h = 0; h < 512; h++) a2 = fmaf(v1s[h], W2[h*H2 + tid], a2);
        g_v2[b*H2 + tid] = 1.0f / (1.0f + __expf(-a2));
    }
}

// ---------------- GEMM: P = exp(v2 @ Wout + bout) -> fp16, cp.async 4-stage, A in smem ----------------
__device__ __forceinline__ void mma8(float* c, uint32_t a0, uint32_t a1, uint32_t a2, uint32_t a3,
                                     uint32_t b0, uint32_t b1) {
    asm volatile(
        "mma.sync.aligned.m16n8k8.row.col.f32.tf32.tf32.f32 "
        "{%0,%1,%2,%3},{%4,%5,%6,%7},{%8,%9},{%0,%1,%2,%3};"
        : "+f"(c[0]), "+f"(c[1]), "+f"(c[2]), "+f"(c[3])
        : "r"(a0), "r"(a1), "r"(a2), "r"(a3), "r"(b0), "r"(b1));
}

__device__ __forceinline__ void cp16(uint32_t saddr, const void* gptr) {
    asm volatile("cp.async.cg.shared.global [%0], [%1], 16;" :: "r"(saddr), "l"(gptr));
}

__global__ void __launch_bounds__(256, 2) k_gemm(const float* __restrict__ Wout,
                                                 const float* __restrict__ bout) {
    extern __shared__ __align__(16) unsigned char smem_raw[];
    float* sA = (float*)smem_raw;                                   // [64][260]
    float (*sB)[8][264] = (float (*)[8][264])(smem_raw + SMEM_B_OFF);
    __half2 (*sO)[132] = (__half2 (*)[132])(smem_raw + SMEM_B_OFF);
    uint32_t sbbase = (uint32_t)__cvta_generic_to_shared(smem_raw + SMEM_B_OFF);

    int tid = threadIdx.x, wid = tid >> 5, lane = tid & 31;
    int gid = lane >> 2, tig = lane & 3;
    int n0 = blockIdx.x * 256;

    int kr = tid >> 5;            // 0..7 k-row within stage
    int c0 = (tid & 31) * 8;      // 0..248 col

    // stage A once: sA[m][k], row stride 260 (bank = gid*4+tig -> conflict-free frags)
    #pragma unroll
    for (int ii = 0; ii < 64; ii++) {
        int idx = ii*256 + tid;
        int m = idx >> 8, k = idx & 255;
        sA[m*260 + k] = g_v2[idx];
    }

    float c[4][4][4];
    #pragma unroll
    for (int mt = 0; mt < 4; mt++)
        #pragma unroll
        for (int nt = 0; nt < 4; nt++)
            { c[mt][nt][0]=0.f; c[mt][nt][1]=0.f; c[mt][nt][2]=0.f; c[mt][nt][3]=0.f; }

    // prologue: issue stages 0..2
    #pragma unroll
    for (int s = 0; s < 3; s++) {
        const float* src = Wout + (size_t)(s*8 + kr)*ZS + n0 + c0;
        uint32_t dst = sbbase + (uint32_t)((s*8 + kr)*264 + c0) * 4u;
        cp16(dst, src);
        cp16(dst + 16, src + 4);
        asm volatile("cp.async.commit_group;");
    }
    __syncthreads();   // sA staged before any warp reads it

    for (int j = 0; j < 32; j++) {
        // tail-exact waits: guarantee stage j has landed.
        // committed groups = 3 + min(j,29); stage j is (j+1)-th group.
        if (j < 30)      asm volatile("cp.async.wait_group 2;");
        else if (j == 30) asm volatile("cp.async.wait_group 1;");
        else              asm volatile("cp.async.wait_group 0;");
        __syncthreads();
        if (j + 3 < 32) {
            int s = (j + 3) & 3;
            const float* src = Wout + (size_t)((j+3)*8 + kr)*ZS + n0 + c0;
            uint32_t dst = sbbase + (uint32_t)((s*8 + kr)*264 + c0) * 4u;
            cp16(dst, src);
            cp16(dst + 16, src + 4);
            asm volatile("cp.async.commit_group;");
        }
        int buf = j & 3;
        int k0 = j * 8;
        uint32_t a0[4], a1[4], a2[4], a3[4];
        #pragma unroll
        for (int mt = 0; mt < 4; mt++) {
            a0[mt] = __float_as_uint(sA[(mt*16+gid  )*260 + k0 + tig    ]);
            a1[mt] = __float_as_uint(sA[(mt*16+gid+8)*260 + k0 + tig    ]);
            a2[mt] = __float_as_uint(sA[(mt*16+gid  )*260 + k0 + tig + 4]);
            a3[mt] = __float_as_uint(sA[(mt*16+gid+8)*260 + k0 + tig + 4]);
        }
        #pragma unroll
        for (int nt = 0; nt < 4; nt++) {
            int colb = wid*32 + nt*8 + gid;
            uint32_t b0 = __float_as_uint(sB[buf][tig  ][colb]);
            uint32_t b1 = __float_as_uint(sB[buf][tig+4][colb]);
            #pragma unroll
            for (int mt = 0; mt < 4; mt++)
                mma8(c[mt][nt], a0[mt], a1[mt], a2[mt], a3[mt], b0, b1);
        }
    }
    __syncthreads();   // all reads of sB done before epilogue reuses smem

    // epilogue: exp(c + bout) -> half2, stage in smem, coalesced copy out
    #pragma unroll
    for (int nt = 0; nt < 4; nt++) {
        int colp = wid*16 + nt*4 + tig;
        float bo0 = bout[n0 + colp*2];
        float bo1 = bout[n0 + colp*2 + 1];
        #pragma unroll
        for (int mt = 0; mt < 4; mt++) {
            int r0 = mt*16 + gid;
            sO[r0  ][colp] = __floats2half2_rn(__expf(c[mt][nt][0]+bo0), __expf(c[mt][nt][1]+bo1));
            sO[r0+8][colp] = __floats2half2_rn(__expf(c[mt][nt][2]+bo0), __expf(c[mt][nt][3]+bo1));
        }
    }
    __syncthreads();
    int r = tid >> 2;
    #pragma unroll
    for (int pass = 0; pass < 8; pass++) {
        int u = (tid & 3) + 4*pass;
        uint4 v = *(uint4*)&sO[r][u*4];
        ((uint4*)(g_P + (size_t)r*ZS + n0))[u] = v;
    }
}

// ---------------- helpers ----------------
__device__ __forceinline__ void unpack8(uint4 q, float* p) {
    float2 f;
    f = __half22float2(*(__half2*)&q.x); p[0]=f.x; p[1]=f.y;
    f = __half22float2(*(__half2*)&q.y); p[2]=f.x; p[3]=f.y;
    f = __half22float2(*(__half2*)&q.z); p[4]=f.x; p[5]=f.y;
    f = __half22float2(*(__half2*)&q.w); p[6]=f.x; p[7]=f.y;
}

// ---------------- persistent Sinkhorn, 2 CTAs/batch with cross-CTA barrier ----------------
__global__ void __launch_bounds__(512, 1) k_sinkp2() {
    __shared__ float s_ew[Ss];
    __shared__ float s_col[Ss];
    __shared__ float s_elp2[Ss];
    __shared__ float s_elp1h[Ss];
    __shared__ float s_part[16][Ss];
    __shared__ float s_red[Ss];

    int b = blockIdx.x >> 1, half = blockIdx.x & 1;
    int tid = threadIdx.x;
    int w = tid >> 5, lane = tid & 31;

    s_elp2[tid]  = g_elp2[b*Ss + tid];
    s_elp1h[tid] = g_elp1[half*512 + tid];
    __syncthreads();

    const uint4* Pb = (const uint4*)(g_P + (size_t)b*ZS);
    float my_part = 0.f;

    for (int it = 0; it <= 10; it++) {
        float ew;
        if (it == 0) ew = 1.0f;
        else {
            float other = g_cph[1 - half][b*Ss + tid];
            s_col[tid] = my_part + other;
            ew = s_elp2[tid] / (my_part + other);
        }
        s_ew[tid] = ew;
        __syncthreads();

        float ewr[16], colacc[16];
        #pragma unroll
        for (int i = 0; i < 8; i++) {
            ewr[i]   = s_ew[8*lane + i];
            ewr[8+i] = s_ew[256 + 8*lane + i];
            colacc[i] = 0.f; colacc[8+i] = 0.f;
        }
        #pragma unroll
        for (int rq = 0; rq < 8; rq++) {
            int zl = w*32 + rq*4;
            uint4 q[8];
            #pragma unroll
            for (int rr = 0; rr < 4; rr++) {
                const uint4* row = Pb + (size_t)(half*512 + zl + rr)*64;
                q[2*rr]   = row[lane];
                q[2*rr+1] = row[lane + 32];
            }
            #pragma unroll
            for (int rr = 0; rr < 4; rr++) {
                float p[16];
                unpack8(q[2*rr], p); unpack8(q[2*rr+1], p+8);
                float rs = 0.f;
                #pragma unroll
                for (int i = 0; i < 16; i++) rs = fmaf(p[i], ewr[i], rs);
                #pragma unroll
                for (int o = 16; o > 0; o >>= 1) rs += __shfl_xor_sync(0xFFFFFFFFu, rs, o);
                float irs = 1.0f / rs;
                int zg = half*512 + zl + rr;
                if (it == 10 && lane == 0) g_iR[b*Zz + zg] = irs;
                float ea = s_elp1h[zl + rr] * irs;
                #pragma unroll
                for (int i = 0; i < 16; i++) colacc[i] = fmaf(p[i], ea, colacc[i]);
            }
        }
        *(float4*)&s_part[w][8*lane]           = make_float4(colacc[0],  colacc[1],  colacc[2],  colacc[3]);
        *(float4*)&s_part[w][8*lane + 4]       = make_float4(colacc[4],  colacc[5],  colacc[6],  colacc[7]);
        *(float4*)&s_part[w][256 + 8*lane]     = make_float4(colacc[8],  colacc[9],  colacc[10], colacc[11]);
        *(float4*)&s_part[w][256 + 8*lane + 4] = make_float4(colacc[12], colacc[13], colacc[14], colacc[15]);
        __syncthreads();
        float sum = 0.f;
        #pragma unroll
        for (int ww = 0; ww < 16; ww++) sum += s_part[ww][tid];
        my_part = sum;
        g_cph[half][b*Ss + tid] = sum;
        __syncthreads();
        if (tid == 0) {
            __threadfence();
            atomicAdd(&g_bar[b], 1);
            int target = 2 * (it + 1);
            while (atomicAdd(&g_bar[b], 0) < target) { }
            __threadfence();
        }
        __syncthreads();
    }

    float other = g_cph[1 - half][b*Ss + tid];
    float colsum = my_part + other;
    float A = s_elp2[tid] / (s_ew[tid] * colsum);
    s_red[tid] = A; __syncthreads();
    for (int o = 256; o > 0; o >>= 1) { if (tid < o) s_red[tid] = fmaxf(s_red[tid], s_red[tid+o]); __syncthreads(); }
    float mx = s_red[0];
    if (half == 0) g_u[b*Ss + tid] = s_ew[tid] * A / mx;
}

// ---------------- fused keep+final ----------------
__global__ void __launch_bounds__(256, 4) k_kf(float* __restrict__ out) {
    int b = blockIdx.y, chunk = blockIdx.x, tid = threadIdx.x;
    __shared__ float s_u[Ss];
    __shared__ float s_e2[Ss];
    #pragma unroll
    for (int h = 0; h < 2; h++) {
        int s = tid + 256*h;
        s_u[s]  = g_u[b*Ss + s];
        s_e2[s] = g_elp2[b*Ss + s];
    }
    __syncthreads();
    int wid = tid >> 5, lane = tid & 31;
    float ur[16], er[16];
    #pragma unroll
    for (int i = 0; i < 8; i++) {
        ur[i]   = s_u[8*lane + i];    ur[8+i] = s_u[256 + 8*lane + i];
        er[i]   = s_e2[8*lane + i];   er[8+i] = s_e2[256 + 8*lane + i];
    }
    const uint4* Pb = (const uint4*)(g_P + (size_t)b*ZS);
    float* Ob = out + (size_t)b*ZS;
    #pragma unroll
    for (int r = 0; r < 8; r++) {
        int z = chunk*64 + wid*8 + r;
        uint4 q0 = Pb[(size_t)z*64 + lane];
        uint4 q1 = Pb[(size_t)z*64 + 32 + lane];
        float p[16];
        unpack8(q0, p); unpack8(q1, p+8);
        float ks = 0.f;
        #pragma unroll
        for (int i = 0; i < 16; i++) ks = fmaf(p[i], ur[i], ks);
        #pragma unroll
        for (int o = 16; o > 0; o >>= 1) ks += __shfl_xor_sync(0xFFFFFFFFu, ks, o);
        float iR = g_iR[b*Zz + z];
        float K = iR * ks;
        float eres = fmaxf(0.f, 1.f - K);
        float l1 = g_lp1[z];
        float v[16];
        #pragma unroll
        for (int i = 0; i < 16; i++)
            v[i] = l1 + __logf(fmaf(p[i], ur[i]*iR, eres*er[i]));
        float* o0 = Ob + (size_t)z*512 + 8*lane;
        float* o1 = o0 + 256;
        *(float4*)(o0    ) = make_float4(v[0], v[1], v[2], v[3]);
        *(float4*)(o0 + 4) = make_float4(v[4], v[5], v[6], v[7]);
        *(float4*)(o1    ) = make_float4(v[8], v[9], v[10], v[11]);
        *(float4*)(o1 + 4) = make_float4(v[12], v[13], v[14], v[15]);
    }
}

// ---------------- launch ----------------
extern "C" void kernel_launch(void* const* d_in, const int* in_sizes, int n_in,
                              void* d_out, int out_size) {
    const float* s_logits = (const float*)d_in[0];
    const float* W1   = (const float*)d_in[1];
    const float* b1   = (const float*)d_in[2];
    const float* W2   = (const float*)d_in[3];
    const float* b2   = (const float*)d_in[4];
    const float* Wout = (const float*)d_in[5];
    const float* bout = (const float*)d_in[6];
    const float* prior= (const float*)d_in[7];
    float* out = (float*)d_out;
    (void)in_sizes; (void)n_in; (void)out_size;

    // unconditional (no call-count guards); host-side attribute set, capture-safe
    cudaFuncSetAttribute(k_gemm, cudaFuncAttributeMaxDynamicSharedMemorySize, SMEM_TOTAL_GEMM);

    k_zero<<<1, Bb>>>();
    k_prior<<<1, 1024>>>(prior);
    k_mlp<<<Bb, 512>>>(s_logits, W1, b1, W2, b2);
    k_gemm<<<2048, 256, SMEM_TOTAL_GEMM>>>(Wout, bout);
    k_sinkp2<<<2*Bb, 512>>>();
    k_kf<<<dim3(16, Bb), 256>>>(out);
}